// round 8
// baseline (speedup 1.0000x reference)
#include <cuda_runtime.h>
#include <math.h>

// Problem constants
#define NN   10000
#define EE   320000
#define LEAK 0.1f
#define LNEPS 1e-5f

// ---------------------------------------------------------------------------
// Device scratch (allocation-free: static __device__ globals)
// ---------------------------------------------------------------------------
__device__ float g_hidden[(size_t)NN * 512];  // [h0 | h1 | h2 | h3] per row
__device__ float g_z[(size_t)NN * 256];       // xc + agg
__device__ float g_t1[(size_t)NN * 256];
__device__ int   g_src[EE];
__device__ int   g_dst[EE];
__device__ int   g_is64;
// CSR by destination node
__device__ int   g_deg[NN];
__device__ int   g_fill[NN];
__device__ int   g_row_off[NN + 1];
__device__ int   g_csr_src[EE];
__device__ float g_csr_a[EE];

// ---------------------------------------------------------------------------
// edge_index dtype detection: int64 (values in [0,10000)) => every odd int32
// word is zero; int32 => 4096 random node ids all-zero is impossible.
// ---------------------------------------------------------------------------
__global__ void detect_idx_kernel(const int* __restrict__ p) {
    __shared__ int sh[256];
    int acc = 0;
    for (int i = threadIdx.x; i < 4096; i += 256) acc |= p[2 * i + 1];
    sh[threadIdx.x] = acc;
    __syncthreads();
    for (int s = 128; s > 0; s >>= 1) {
        if (threadIdx.x < s) sh[threadIdx.x] |= sh[threadIdx.x + s];
        __syncthreads();
    }
    if (threadIdx.x == 0) g_is64 = (sh[0] == 0) ? 1 : 0;
}

__global__ void convert_idx_kernel(const int* __restrict__ p) {
    int e = blockIdx.x * blockDim.x + threadIdx.x;
    if (e >= EE) return;
    int s, d;
    if (g_is64) {
        s = p[2 * e];
        d = p[2 * (EE + e)];
    } else {
        s = p[e];
        d = p[EE + e];
    }
    g_src[e] = s;
    g_dst[e] = d;
    atomicAdd(&g_deg[d], 1);
}

// ---------------------------------------------------------------------------
// Exclusive scan of g_deg -> g_row_off  (single block, 1024 threads)
// ---------------------------------------------------------------------------
__global__ void scan_kernel() {
    __shared__ int warpsums[32];
    __shared__ int s_carry;
    int tid  = threadIdx.x;
    int lane = tid & 31;
    int wid  = tid >> 5;
    if (tid == 0) s_carry = 0;
    __syncthreads();

    for (int base = 0; base < NN; base += 1024) {
        int idx = base + tid;
        int v = (idx < NN) ? g_deg[idx] : 0;
        int orig = v;
#pragma unroll
        for (int s = 1; s < 32; s <<= 1) {
            int n = __shfl_up_sync(0xffffffffu, v, s);
            if (lane >= s) v += n;
        }
        if (lane == 31) warpsums[wid] = v;
        __syncthreads();
        if (wid == 0) {
            int w = warpsums[lane];
#pragma unroll
            for (int s = 1; s < 32; s <<= 1) {
                int n = __shfl_up_sync(0xffffffffu, w, s);
                if (lane >= s) w += n;
            }
            warpsums[lane] = w;
        }
        __syncthreads();
        int add = s_carry + ((wid > 0) ? warpsums[wid - 1] : 0);
        if (idx < NN) g_row_off[idx] = add + v - orig;  // exclusive
        __syncthreads();
        if (tid == 0) s_carry += warpsums[31];
        __syncthreads();
    }
    if (tid == 0) g_row_off[NN] = s_carry;  // == EE
}

// ---------------------------------------------------------------------------
// Fill CSR buckets: g_csr_src / g_csr_a grouped by destination node.
// ---------------------------------------------------------------------------
__global__ void fill_csr_kernel(const float* __restrict__ ea) {
    int e = blockIdx.x * blockDim.x + threadIdx.x;
    if (e >= EE) return;
    int d = g_dst[e];
    int pos = g_row_off[d] + atomicAdd(&g_fill[d], 1);
    g_csr_src[pos] = g_src[e];
    g_csr_a[pos]   = ea[e];
}

// ---------------------------------------------------------------------------
// Fused z = xc + segment_sum(relu(xc[src] + a*eW + eB)).
// One block (64 threads) per destination node; thread t owns feature dims
// 4t..4t+3 via float4. dims <128 come from x, >=128 from hidden slice hoff.
// Edge (src, a) pairs staged through smem in chunks of 64. No atomics.
// ---------------------------------------------------------------------------
#define GCH 64
__global__ void gather_kernel(const float* __restrict__ x, int hoff,
                              const float* __restrict__ eW,
                              const float* __restrict__ eB) {
    __shared__ int   s_src[GCH];
    __shared__ float s_a[GCH];

    int n = blockIdx.x;
    int t = threadIdx.x;      // 0..63
    int d = t << 2;           // feature dim base (0,4,...,252)

    float4 w  = *(const float4*)(eW + d);
    float4 bb = *(const float4*)(eB + d);

    const float* featbase;
    size_t fstride;
    if (d < 128) { featbase = x + d;                       fstride = 128; }
    else         { featbase = g_hidden + hoff + (d - 128); fstride = 512; }

    float4 acc = *(const float4*)(featbase + (size_t)n * fstride);  // self term

    int p0 = g_row_off[n];
    int p1 = g_row_off[n + 1];

    for (int c0 = p0; c0 < p1; c0 += GCH) {
        int cnt = min(GCH, p1 - c0);
        if (t < cnt) {
            s_src[t] = g_csr_src[c0 + t];
            s_a[t]   = g_csr_a[c0 + t];
        }
        __syncthreads();
#pragma unroll 8
        for (int i = 0; i < cnt; i++) {
            int   s = s_src[i];      // uniform across block -> LDS broadcast
            float a = s_a[i];
            float4 v = *(const float4*)(featbase + (size_t)s * fstride);
            acc.x += fmaxf(fmaf(a, w.x, bb.x) + v.x, 0.f);
            acc.y += fmaxf(fmaf(a, w.y, bb.y) + v.y, 0.f);
            acc.z += fmaxf(fmaf(a, w.z, bb.z) + v.z, 0.f);
            acc.w += fmaxf(fmaf(a, w.w, bb.w) + v.w, 0.f);
        }
        __syncthreads();
    }
    *(float4*)(g_z + (size_t)n * 256 + d) = acc;
}

// ---------------------------------------------------------------------------
// SGEMM 64x128 tile (full N=128), BK=8, 256 threads, 8x4 microtile,
// DOUBLE-BUFFERED smem. For the N=128 GEMMs (h0, out).
// B-path smem accesses are 16B lane-contiguous (conflict-free).
// Requirements: N == 128 (grid.x == 1), K % 8 == 0, ldb >= 128.
// ---------------------------------------------------------------------------
__global__ void __launch_bounds__(256, 2)
gemm64x128_kernel(const float* __restrict__ A, int lda,
                  const float* __restrict__ B, int ldb,
                  const float* __restrict__ bias,
                  float* __restrict__ C, int ldc,
                  int M, int K, int act) {
    __shared__ float As[2][8][64];
    __shared__ float Bs[2][8][128];

    int tid = threadIdx.x;
    int tx = tid & 31;        // 0..31 -> col group (4 cols each)
    int ty = tid >> 5;        // 0..7  -> warp = row group (8 rows each)
    int rowBase = blockIdx.y * 64;

    int a_r = tid >> 2;
    int a_k = (tid & 3) << 1;
    int b_k = tid >> 5;
    int b_c = (tid & 31) << 2;

    int gr = rowBase + a_r;
    bool a_ok = (gr < M);
    const float* Aptr = A + (size_t)((gr < M) ? gr : 0) * lda + a_k;
    const float* Bptr = B + (size_t)b_k * ldb + b_c;

    float acc[8][4];
#pragma unroll
    for (int i = 0; i < 8; i++)
#pragma unroll
        for (int j = 0; j < 4; j++) acc[i][j] = 0.f;

    float2 av = a_ok ? *(const float2*)(Aptr) : make_float2(0.f, 0.f);
    float4 bv = *(const float4*)(Bptr);
    As[0][a_k + 0][a_r] = av.x;
    As[0][a_k + 1][a_r] = av.y;
    *(float4*)&Bs[0][b_k][b_c] = bv;
    __syncthreads();

    int buf = 0;
    for (int k0 = 0; k0 < K; k0 += 8) {
        bool more = (k0 + 8) < K;
        if (more) {
            av = a_ok ? *(const float2*)(Aptr + k0 + 8) : make_float2(0.f, 0.f);
            bv = *(const float4*)(Bptr + (size_t)(k0 + 8) * ldb);
        }

#pragma unroll
        for (int k = 0; k < 8; k++) {
            float ar[8], br[4];
            *(float4*)&ar[0] = *(const float4*)&As[buf][k][ty * 8];
            *(float4*)&ar[4] = *(const float4*)&As[buf][k][ty * 8 + 4];
            *(float4*)&br[0] = *(const float4*)&Bs[buf][k][tx * 4];
#pragma unroll
            for (int i = 0; i < 8; i++)
#pragma unroll
                for (int j = 0; j < 4; j++) acc[i][j] = fmaf(ar[i], br[j], acc[i][j]);
        }

        if (more) {
            int nb = buf ^ 1;
            As[nb][a_k + 0][a_r] = av.x;
            As[nb][a_k + 1][a_r] = av.y;
            *(float4*)&Bs[nb][b_k][b_c] = bv;
            __syncthreads();
            buf = nb;
        }
    }

    float4 bia = *(const float4*)(bias + tx * 4);
#pragma unroll
    for (int i = 0; i < 8; i++) {
        int r = rowBase + ty * 8 + i;
        if (r >= M) continue;
        float o0 = acc[i][0] + bia.x;
        float o1 = acc[i][1] + bia.y;
        float o2 = acc[i][2] + bia.z;
        float o3 = acc[i][3] + bia.w;
        if (act == 1) {
            o0 = (o0 > 0.f) ? o0 : LEAK * o0;
            o1 = (o1 > 0.f) ? o1 : LEAK * o1;
            o2 = (o2 > 0.f) ? o2 : LEAK * o2;
            o3 = (o3 > 0.f) ? o3 : LEAK * o3;
        }
        *(float4*)(C + (size_t)r * ldc + tx * 4) = make_float4(o0, o1, o2, o3);
    }
}

// ---------------------------------------------------------------------------
// Fused W1 GEMM + LayerNorm + leaky:  t1 = leaky(LN(z @ W1 + b1))
// Tile: 64 rows x 256 cols (full N), BK=8, 256 threads, 8 warps.
// Thread cols are TWO 128-apart strips: {tx*4..+3} and {128+tx*4..+3} so all
// Bs LDS.128/STS.128 are 16B lane-contiguous => conflict-free (was 8-way).
// Each warp owns 8 complete rows -> LN reduction is a pure warp shuffle.
// K and ldb fixed at 256.
// ---------------------------------------------------------------------------
__global__ void __launch_bounds__(256, 2)
gemm_w1_ln_kernel(const float* __restrict__ A,       // [M,256] = z
                  const float* __restrict__ B,       // [256,256] = W1
                  const float* __restrict__ bias,    // [256]
                  const float* __restrict__ lng,     // [256]
                  const float* __restrict__ lnb,     // [256]
                  float* __restrict__ C,             // [M,256] = t1
                  int M) {
    __shared__ float As[2][8][64];
    __shared__ float Bs[2][8][256];

    int tid = threadIdx.x;
    int tx = tid & 31;        // 0..31 -> strip col group (4+4 cols)
    int ty = tid >> 5;        // 0..7  -> warp = row group (8 rows each)
    int rowBase = blockIdx.x * 64;

    int a_r = tid >> 2;
    int a_k = (tid & 3) << 1;
    int b_k = tid >> 5;
    int b_c = (tid & 31) << 2;     // strip 0 base; strip 1 = b_c + 128

    int gr = rowBase + a_r;
    bool a_ok = (gr < M);
    const float* Aptr = A + (size_t)((gr < M) ? gr : 0) * 256 + a_k;
    const float* Bptr = B + (size_t)b_k * 256 + b_c;

    float acc[8][8];
#pragma unroll
    for (int i = 0; i < 8; i++)
#pragma unroll
        for (int j = 0; j < 8; j++) acc[i][j] = 0.f;

    float2 av = a_ok ? *(const float2*)(Aptr) : make_float2(0.f, 0.f);
    float4 bv0 = *(const float4*)(Bptr);          // cols b_c..b_c+3
    float4 bv1 = *(const float4*)(Bptr + 128);    // cols 128+b_c..+3
    As[0][a_k + 0][a_r] = av.x;
    As[0][a_k + 1][a_r] = av.y;
    *(float4*)&Bs[0][b_k][b_c]       = bv0;
    *(float4*)&Bs[0][b_k][b_c + 128] = bv1;
    __syncthreads();

    int buf = 0;
    for (int k0 = 0; k0 < 256; k0 += 8) {
        bool more = (k0 + 8) < 256;
        if (more) {
            av  = a_ok ? *(const float2*)(Aptr + k0 + 8) : make_float2(0.f, 0.f);
            bv0 = *(const float4*)(Bptr + (size_t)(k0 + 8) * 256);
            bv1 = *(const float4*)(Bptr + (size_t)(k0 + 8) * 256 + 128);
        }

#pragma unroll
        for (int k = 0; k < 8; k++) {
            float ar[8], br[8];
            *(float4*)&ar[0] = *(const float4*)&As[buf][k][ty * 8];
            *(float4*)&ar[4] = *(const float4*)&As[buf][k][ty * 8 + 4];
            *(float4*)&br[0] = *(const float4*)&Bs[buf][k][tx * 4];         // strip 0
            *(float4*)&br[4] = *(const float4*)&Bs[buf][k][tx * 4 + 128];   // strip 1
#pragma unroll
            for (int i = 0; i < 8; i++)
#pragma unroll
                for (int j = 0; j < 8; j++) acc[i][j] = fmaf(ar[i], br[j], acc[i][j]);
        }

        if (more) {
            int nb = buf ^ 1;
            As[nb][a_k + 0][a_r] = av.x;
            As[nb][a_k + 1][a_r] = av.y;
            *(float4*)&Bs[nb][b_k][b_c]       = bv0;
            *(float4*)&Bs[nb][b_k][b_c + 128] = bv1;
            __syncthreads();
            buf = nb;
        }
    }

    // Epilogue: +bias, per-row LN (warp reduction over all 256 cols: 32 lanes
    // x 8 strip cols), affine + leaky. acc[i][0..3] = cols tx*4..+3,
    // acc[i][4..7] = cols 128+tx*4..+3.
    float4 bia0 = *(const float4*)(bias + tx * 4);
    float4 bia1 = *(const float4*)(bias + tx * 4 + 128);
    float4 g0 = *(const float4*)(lng + tx * 4);
    float4 g1 = *(const float4*)(lng + tx * 4 + 128);
    float4 q0 = *(const float4*)(lnb + tx * 4);
    float4 q1 = *(const float4*)(lnb + tx * 4 + 128);

#pragma unroll
    for (int i = 0; i < 8; i++) {
        acc[i][0] += bia0.x; acc[i][1] += bia0.y;
        acc[i][2] += bia0.z; acc[i][3] += bia0.w;
        acc[i][4] += bia1.x; acc[i][5] += bia1.y;
        acc[i][6] += bia1.z; acc[i][7] += bia1.w;

        float sum = 0.f, sq = 0.f;
#pragma unroll
        for (int j = 0; j < 8; j++) {
            sum += acc[i][j];
            sq = fmaf(acc[i][j], acc[i][j], sq);
        }
#pragma unroll
        for (int s = 16; s > 0; s >>= 1) {
            sum += __shfl_xor_sync(0xffffffffu, sum, s);
            sq  += __shfl_xor_sync(0xffffffffu, sq,  s);
        }
        float mean = sum * (1.f / 256.f);
        float var  = sq * (1.f / 256.f) - mean * mean;
        float rstd = rsqrtf(var + LNEPS);

        int r = rowBase + ty * 8 + i;
        if (r >= M) continue;

        float o[8];
        o[0] = (acc[i][0] - mean) * rstd * g0.x + q0.x;
        o[1] = (acc[i][1] - mean) * rstd * g0.y + q0.y;
        o[2] = (acc[i][2] - mean) * rstd * g0.z + q0.z;
        o[3] = (acc[i][3] - mean) * rstd * g0.w + q0.w;
        o[4] = (acc[i][4] - mean) * rstd * g1.x + q1.x;
        o[5] = (acc[i][5] - mean) * rstd * g1.y + q1.y;
        o[6] = (acc[i][6] - mean) * rstd * g1.z + q1.z;
        o[7] = (acc[i][7] - mean) * rstd * g1.w + q1.w;
#pragma unroll
        for (int j = 0; j < 8; j++) o[j] = (o[j] > 0.f) ? o[j] : LEAK * o[j];

        float* cp = C + (size_t)r * 256 + tx * 4;
        *(float4*)(cp)       = make_float4(o[0], o[1], o[2], o[3]);
        *(float4*)(cp + 128) = make_float4(o[4], o[5], o[6], o[7]);
    }
}

// ---------------------------------------------------------------------------
// Fused W2+W3:  h = (leaky(t1 @ W2 + b2)) @ W3 + b3, 64-row tile per block.
// Phase 1: t2 tile (64x256) via strip-mapped mainloop (conflict-free smem),
//          bias+leaky applied, parked in smem.
// Phase 2: h tile (64x128) = t2s @ W3 + b3; W3 double-buffered through the
//          reused Bs area; t2s reads are same-address-per-warp (broadcast).
// Dynamic smem: t2s 64KB + As 4KB + Bs 16KB = 84KB; 2 CTAs/SM.
// ---------------------------------------------------------------------------
#define W23_SMEM_BYTES (64 * 256 * 4 + 2 * 8 * 64 * 4 + 2 * 8 * 256 * 4)  // 86016

__global__ void __launch_bounds__(256, 2)
gemm_w23_kernel(const float* __restrict__ A,       // [M,256] = t1
                const float* __restrict__ W2,      // [256,256]
                const float* __restrict__ b2,      // [256]
                const float* __restrict__ W3,      // [256,128]
                const float* __restrict__ b3,      // [128]
                float* __restrict__ C,             // h slice, ldc = 512
                int ldc, int M) {
    extern __shared__ float sdyn[];
    float* t2s = sdyn;                         // [64][256]
    float* Asb = sdyn + 64 * 256;              // [2][8][64]
    float* Bsb = Asb + 2 * 8 * 64;             // [2][8][256]
    float* Wsb = Bsb;                          // overlay [2][8][128] (phase 2)
#define AS(b, k, r) Asb[(b) * 512 + (k) * 64 + (r)]
#define BS(b, k, c) Bsb[(b) * 2048 + (k) * 256 + (c)]
#define WS(b, k, c) Wsb[(b) * 1024 + (k) * 128 + (c)]
#define T2S(r, c)   t2s[(r) * 256 + (c)]

    int tid = threadIdx.x;
    int tx = tid & 31;        // 0..31 -> strip col group
    int ty = tid >> 5;        // 0..7  -> warp = row group (8 rows each)
    int rowBase = blockIdx.x * 64;

    int a_r = tid >> 2;
    int a_k = (tid & 3) << 1;
    int b_k = tid >> 5;
    int b_c = (tid & 31) << 2;     // strip 0 base; strip 1 = b_c + 128

    int gr = rowBase + a_r;
    bool a_ok = (gr < M);
    const float* Aptr = A + (size_t)((gr < M) ? gr : 0) * 256 + a_k;
    const float* Bptr = W2 + (size_t)b_k * 256 + b_c;

    // ---------------- Phase 1: t2 = leaky(t1 @ W2 + b2) -> smem ----------------
    float acc[8][8];
#pragma unroll
    for (int i = 0; i < 8; i++)
#pragma unroll
        for (int j = 0; j < 8; j++) acc[i][j] = 0.f;

    float2 av = a_ok ? *(const float2*)(Aptr) : make_float2(0.f, 0.f);
    float4 bv0 = *(const float4*)(Bptr);
    float4 bv1 = *(const float4*)(Bptr + 128);
    AS(0, a_k + 0, a_r) = av.x;
    AS(0, a_k + 1, a_r) = av.y;
    *(float4*)&BS(0, b_k, b_c)       = bv0;
    *(float4*)&BS(0, b_k, b_c + 128) = bv1;
    __syncthreads();

    int buf = 0;
    for (int k0 = 0; k0 < 256; k0 += 8) {
        bool more = (k0 + 8) < 256;
        if (more) {
            av  = a_ok ? *(const float2*)(Aptr + k0 + 8) : make_float2(0.f, 0.f);
            bv0 = *(const float4*)(Bptr + (size_t)(k0 + 8) * 256);
            bv1 = *(const float4*)(Bptr + (size_t)(k0 + 8) * 256 + 128);
        }

#pragma unroll
        for (int k = 0; k < 8; k++) {
            float ar[8], br[8];
            *(float4*)&ar[0] = *(const float4*)&AS(buf, k, ty * 8);
            *(float4*)&ar[4] = *(const float4*)&AS(buf, k, ty * 8 + 4);
            *(float4*)&br[0] = *(const float4*)&BS(buf, k, tx * 4);         // strip 0
            *(float4*)&br[4] = *(const float4*)&BS(buf, k, tx * 4 + 128);   // strip 1
#pragma unroll
            for (int i = 0; i < 8; i++)
#pragma unroll
                for (int j = 0; j < 8; j++) acc[i][j] = fmaf(ar[i], br[j], acc[i][j]);
        }

        if (more) {
            int nb = buf ^ 1;
            AS(nb, a_k + 0, a_r) = av.x;
            AS(nb, a_k + 1, a_r) = av.y;
            *(float4*)&BS(nb, b_k, b_c)       = bv0;
            *(float4*)&BS(nb, b_k, b_c + 128) = bv1;
            __syncthreads();
            buf = nb;
        }
    }

    // bias + leaky, park t2 tile in smem (strip-mapped stores, conflict-free)
    {
        float4 bia0 = *(const float4*)(b2 + tx * 4);
        float4 bia1 = *(const float4*)(b2 + tx * 4 + 128);
#pragma unroll
        for (int i = 0; i < 8; i++) {
            float o[8];
            o[0] = acc[i][0] + bia0.x; o[1] = acc[i][1] + bia0.y;
            o[2] = acc[i][2] + bia0.z; o[3] = acc[i][3] + bia0.w;
            o[4] = acc[i][4] + bia1.x; o[5] = acc[i][5] + bia1.y;
            o[6] = acc[i][6] + bia1.z; o[7] = acc[i][7] + bia1.w;
#pragma unroll
            for (int j = 0; j < 8; j++) o[j] = (o[j] > 0.f) ? o[j] : LEAK * o[j];
            float* tp = &T2S(ty * 8 + i, tx * 4);
            *(float4*)(tp)       = make_float4(o[0], o[1], o[2], o[3]);
            *(float4*)(tp + 128) = make_float4(o[4], o[5], o[6], o[7]);
        }
    }
    __syncthreads();   // t2s complete; Bs mainloop reads all done -> reuse as Ws

    // ---------------- Phase 2: h = t2s @ W3 + b3 ----------------
    float acc2[8][4];
#pragma unroll
    for (int i = 0; i < 8; i++)
#pragma unroll
        for (int j = 0; j < 4; j++) acc2[i][j] = 0.f;

    float4 wv = *(const float4*)(W3 + (size_t)b_k * 128 + b_c);
    *(float4*)&WS(0, b_k, b_c) = wv;
    __syncthreads();

    buf = 0;
    for (int k0 = 0; k0 < 256; k0 += 8) {
        bool more = (k0 + 8) < 256;
        if (more)
            wv = *(const float4*)(W3 + (size_t)(k0 + 8 + b_k) * 128 + b_c);

#pragma unroll
        for (int k = 0; k < 8; k++) {
            float ar[8], br[4];
#pragma unroll
            for (int i = 0; i < 8; i++) ar[i] = T2S(ty * 8 + i, k0 + k);  // broadcast
            *(float4*)&br[0] = *(const float4*)&WS(buf, k, tx * 4);
#pragma unroll
            for (int i = 0; i < 8; i++)
#pragma unroll
                for (int j = 0; j < 4; j++) acc2[i][j] = fmaf(ar[i], br[j], acc2[i][j]);
        }

        if (more) {
            int nb = buf ^ 1;
            *(float4*)&WS(nb, b_k, b_c) = wv;
            __syncthreads();
            buf = nb;
        }
    }

    float4 bia = *(const float4*)(b3 + tx * 4);
#pragma unroll
    for (int i = 0; i < 8; i++) {
        int r = rowBase + ty * 8 + i;
        if (r >= M) continue;
        *(float4*)(C + (size_t)r * ldc + tx * 4) =
            make_float4(acc2[i][0] + bia.x, acc2[i][1] + bia.y,
                        acc2[i][2] + bia.z, acc2[i][3] + bia.w);
    }
#undef AS
#undef BS
#undef WS
#undef T2S
}

// ---------------------------------------------------------------------------
// Host launcher
// ---------------------------------------------------------------------------
extern "C" void kernel_launch(void* const* d_in, const int* in_sizes, int n_in,
                              void* d_out, int out_size) {
    const float* x     = (const float*)d_in[0];
    const int*   ei    = (const int*)d_in[1];   // int32 view; stride auto-detected
    const float* ea    = (const float*)d_in[2];
    const float* in_W  = (const float*)d_in[3];
    const float* in_b  = (const float*)d_in[4];
    const float* eW    = (const float*)d_in[5];   // [3,256]
    const float* eB    = (const float*)d_in[6];   // [3,256]
    const float* W1    = (const float*)d_in[7];   // [3,256,256]
    const float* b1    = (const float*)d_in[8];   // [3,256]
    const float* ln_g  = (const float*)d_in[9];   // [3,256]
    const float* ln_b  = (const float*)d_in[10];  // [3,256]
    const float* W2    = (const float*)d_in[11];  // [3,256,256]
    const float* b2    = (const float*)d_in[12];  // [3,256]
    const float* W3    = (const float*)d_in[13];  // [3,256,128]
    const float* b3    = (const float*)d_in[14];  // [3,128]
    const float* out_W = (const float*)d_in[15];  // [512,128]
    const float* out_b = (const float*)d_in[16];  // [128]
    float* out = (float*)d_out;

    float *hid, *z, *t1;
    int *deg, *fill;
    cudaGetSymbolAddress((void**)&hid,  g_hidden);
    cudaGetSymbolAddress((void**)&z,    g_z);
    cudaGetSymbolAddress((void**)&t1,   g_t1);
    cudaGetSymbolAddress((void**)&deg,  g_deg);
    cudaGetSymbolAddress((void**)&fill, g_fill);

    cudaFuncSetAttribute(gemm_w23_kernel,
                         cudaFuncAttributeMaxDynamicSharedMemorySize,
                         W23_SMEM_BYTES);

    dim3 blk(256);
    int mTiles64 = (NN + 63) / 64;    // 157

    // ---- CSR build (once per launch, reused by all 3 layers) ----
    cudaMemsetAsync(deg,  0, NN * sizeof(int));
    cudaMemsetAsync(fill, 0, NN * sizeof(int));
    detect_idx_kernel<<<1, 256>>>(ei);
    convert_idx_kernel<<<(EE + 255) / 256, 256>>>(ei);
    scan_kernel<<<1, 1024>>>();
    fill_csr_kernel<<<(EE + 255) / 256, 256>>>(ea);

    // h0 = x @ in_W + in_b  ->  hidden[:, 0:128]
    gemm64x128_kernel<<<dim3(1, mTiles64), blk>>>(x, 128, in_W, 128, in_b,
                                                  hid, 512, NN, 128, 0);

    for (int l = 0; l < 3; l++) {
        int hoff = l * 128;
        // z = xc + segment_sum(relu(xc[src] + edge_proj))   (atomic-free, float4)
        gather_kernel<<<NN, 64>>>(x, hoff, eW + l * 256, eB + l * 256);
        // t1 = leaky(LN(z @ W1 + b1))   (fused epilogue)
        gemm_w1_ln_kernel<<<mTiles64, blk>>>(z, W1 + (size_t)l * 256 * 256,
                                             b1 + l * 256, ln_g + l * 256,
                                             ln_b + l * 256, t1, NN);
        // h_{l+1} = leaky(t1 @ W2 + b2) @ W3 + b3   (fused, t2 never hits gmem)
        gemm_w23_kernel<<<mTiles64, blk, W23_SMEM_BYTES>>>(
            t1, W2 + (size_t)l * 256 * 256, b2 + l * 256,
            W3 + (size_t)l * 256 * 128, b3 + l * 128,
            hid + (l + 1) * 128, 512, NN);
    }

    // out = hidden @ out_W + out_b
    gemm64x128_kernel<<<dim3(1, mTiles64), blk>>>(hid, 512, out_W, 128, out_b,
                                                  out, 128, NN, 512, 0);
}

// round 11
// speedup vs baseline: 1.0215x; 1.0215x over previous
#include <cuda_runtime.h>
#include <math.h>

// Problem constants
#define NN   10000
#define EE   320000
#define LEAK 0.1f
#define LNEPS 1e-5f

typedef unsigned long long u64;

// ---- packed fp32x2 helpers (SASS FFMA2 path; PTX-only, ptxas won't auto-fuse)
__device__ __forceinline__ u64 ffma2(u64 a, u64 b, u64 c) {
    u64 d;
    asm("fma.rn.f32x2 %0, %1, %2, %3;" : "=l"(d) : "l"(a), "l"(b), "l"(c));
    return d;
}
__device__ __forceinline__ u64 pack2(float lo, float hi) {
    u64 d;
    asm("mov.b64 %0, {%1, %2};" : "=l"(d) : "f"(lo), "f"(hi));
    return d;
}
__device__ __forceinline__ float2 unpack2(u64 v) {
    float2 r;
    asm("mov.b64 {%0, %1}, %2;" : "=f"(r.x), "=f"(r.y) : "l"(v));
    return r;
}

// ---------------------------------------------------------------------------
// Device scratch (allocation-free: static __device__ globals)
// ---------------------------------------------------------------------------
__device__ float g_hidden[(size_t)NN * 512];  // [h0 | h1 | h2 | h3] per row
__device__ float g_z[(size_t)NN * 256];       // xc + agg
__device__ float g_t1[(size_t)NN * 256];
__device__ int   g_src[EE];
__device__ int   g_dst[EE];
__device__ int   g_is64;
// CSR by destination node
__device__ int   g_deg[NN];
__device__ int   g_fill[NN];
__device__ int   g_row_off[NN + 1];
__device__ int   g_csr_src[EE];
__device__ float g_csr_a[EE];

// ---------------------------------------------------------------------------
// edge_index dtype detection
// ---------------------------------------------------------------------------
__global__ void detect_idx_kernel(const int* __restrict__ p) {
    __shared__ int sh[256];
    int acc = 0;
    for (int i = threadIdx.x; i < 4096; i += 256) acc |= p[2 * i + 1];
    sh[threadIdx.x] = acc;
    __syncthreads();
    for (int s = 128; s > 0; s >>= 1) {
        if (threadIdx.x < s) sh[threadIdx.x] |= sh[threadIdx.x + s];
        __syncthreads();
    }
    if (threadIdx.x == 0) g_is64 = (sh[0] == 0) ? 1 : 0;
}

__global__ void convert_idx_kernel(const int* __restrict__ p) {
    int e = blockIdx.x * blockDim.x + threadIdx.x;
    if (e >= EE) return;
    int s, d;
    if (g_is64) {
        s = p[2 * e];
        d = p[2 * (EE + e)];
    } else {
        s = p[e];
        d = p[EE + e];
    }
    g_src[e] = s;
    g_dst[e] = d;
    atomicAdd(&g_deg[d], 1);
}

// ---------------------------------------------------------------------------
// Exclusive scan of g_deg -> g_row_off  (single block, 1024 threads)
// ---------------------------------------------------------------------------
__global__ void scan_kernel() {
    __shared__ int warpsums[32];
    __shared__ int s_carry;
    int tid  = threadIdx.x;
    int lane = tid & 31;
    int wid  = tid >> 5;
    if (tid == 0) s_carry = 0;
    __syncthreads();

    for (int base = 0; base < NN; base += 1024) {
        int idx = base + tid;
        int v = (idx < NN) ? g_deg[idx] : 0;
        int orig = v;
#pragma unroll
        for (int s = 1; s < 32; s <<= 1) {
            int n = __shfl_up_sync(0xffffffffu, v, s);
            if (lane >= s) v += n;
        }
        if (lane == 31) warpsums[wid] = v;
        __syncthreads();
        if (wid == 0) {
            int w = warpsums[lane];
#pragma unroll
            for (int s = 1; s < 32; s <<= 1) {
                int n = __shfl_up_sync(0xffffffffu, w, s);
                if (lane >= s) w += n;
            }
            warpsums[lane] = w;
        }
        __syncthreads();
        int add = s_carry + ((wid > 0) ? warpsums[wid - 1] : 0);
        if (idx < NN) g_row_off[idx] = add + v - orig;  // exclusive
        __syncthreads();
        if (tid == 0) s_carry += warpsums[31];
        __syncthreads();
    }
    if (tid == 0) g_row_off[NN] = s_carry;  // == EE
}

// ---------------------------------------------------------------------------
// Fill CSR buckets: g_csr_src / g_csr_a grouped by destination node.
// ---------------------------------------------------------------------------
__global__ void fill_csr_kernel(const float* __restrict__ ea) {
    int e = blockIdx.x * blockDim.x + threadIdx.x;
    if (e >= EE) return;
    int d = g_dst[e];
    int pos = g_row_off[d] + atomicAdd(&g_fill[d], 1);
    g_csr_src[pos] = g_src[e];
    g_csr_a[pos]   = ea[e];
}

// ---------------------------------------------------------------------------
// Fused z = xc + segment_sum(relu(xc[src] + a*eW + eB)). (unchanged, passing)
// ---------------------------------------------------------------------------
#define GCH 64
__global__ void gather_kernel(const float* __restrict__ x, int hoff,
                              const float* __restrict__ eW,
                              const float* __restrict__ eB) {
    __shared__ int   s_src[GCH];
    __shared__ float s_a[GCH];

    int n = blockIdx.x;
    int t = threadIdx.x;      // 0..63
    int d = t << 2;           // feature dim base (0,4,...,252)

    float4 w  = *(const float4*)(eW + d);
    float4 bb = *(const float4*)(eB + d);

    const float* featbase;
    size_t fstride;
    if (d < 128) { featbase = x + d;                       fstride = 128; }
    else         { featbase = g_hidden + hoff + (d - 128); fstride = 512; }

    float4 acc = *(const float4*)(featbase + (size_t)n * fstride);  // self term

    int p0 = g_row_off[n];
    int p1 = g_row_off[n + 1];

    for (int c0 = p0; c0 < p1; c0 += GCH) {
        int cnt = min(GCH, p1 - c0);
        if (t < cnt) {
            s_src[t] = g_csr_src[c0 + t];
            s_a[t]   = g_csr_a[c0 + t];
        }
        __syncthreads();
#pragma unroll 8
        for (int i = 0; i < cnt; i++) {
            int   s = s_src[i];
            float a = s_a[i];
            float4 v = *(const float4*)(featbase + (size_t)s * fstride);
            acc.x += fmaxf(fmaf(a, w.x, bb.x) + v.x, 0.f);
            acc.y += fmaxf(fmaf(a, w.y, bb.y) + v.y, 0.f);
            acc.z += fmaxf(fmaf(a, w.z, bb.z) + v.z, 0.f);
            acc.w += fmaxf(fmaf(a, w.w, bb.w) + v.w, 0.f);
        }
        __syncthreads();
    }
    *(float4*)(g_z + (size_t)n * 256 + d) = acc;
}

// ---------------------------------------------------------------------------
// SGEMM 64x128 tile, BK=8, 256 threads, DOUBLE-BUFFERED, FFMA2 mainloop.
// Accumulators paired over adjacent ROWS (A-pairs free via 64-bit LDS of
// adjacent As entries; 4 B-dups per k). accp[ip][j] = rows (2ip,2ip+1), col j.
// ---------------------------------------------------------------------------
__global__ void __launch_bounds__(256, 2)
gemm64x128_kernel(const float* __restrict__ A, int lda,
                  const float* __restrict__ B, int ldb,
                  const float* __restrict__ bias,
                  float* __restrict__ C, int ldc,
                  int M, int K, int act) {
    __shared__ float As[2][8][64];
    __shared__ float Bs[2][8][128];

    int tid = threadIdx.x;
    int tx = tid & 31;        // 0..31 -> col group (4 cols each)
    int ty = tid >> 5;        // 0..7  -> warp = row group (8 rows each)
    int rowBase = blockIdx.y * 64;

    int a_r = tid >> 2;
    int a_k = (tid & 3) << 1;
    int b_k = tid >> 5;
    int b_c = (tid & 31) << 2;

    int gr = rowBase + a_r;
    bool a_ok = (gr < M);
    const float* Aptr = A + (size_t)((gr < M) ? gr : 0) * lda + a_k;
    const float* Bptr = B + (size_t)b_k * ldb + b_c;

    u64 accp[4][4];
#pragma unroll
    for (int i = 0; i < 4; i++)
#pragma unroll
        for (int j = 0; j < 4; j++) accp[i][j] = 0ULL;

    float2 av = a_ok ? *(const float2*)(Aptr) : make_float2(0.f, 0.f);
    float4 bv = *(const float4*)(Bptr);
    As[0][a_k + 0][a_r] = av.x;
    As[0][a_k + 1][a_r] = av.y;
    *(float4*)&Bs[0][b_k][b_c] = bv;
    __syncthreads();

    int buf = 0;
    for (int k0 = 0; k0 < K; k0 += 8) {
        bool more = (k0 + 8) < K;
        if (more) {
            av = a_ok ? *(const float2*)(Aptr + k0 + 8) : make_float2(0.f, 0.f);
            bv = *(const float4*)(Bptr + (size_t)(k0 + 8) * ldb);
        }

#pragma unroll
        for (int k = 0; k < 8; k++) {
            ulonglong2 ap0 = *(const ulonglong2*)&As[buf][k][ty * 8];     // broadcast
            ulonglong2 ap1 = *(const ulonglong2*)&As[buf][k][ty * 8 + 4];
            u64 arp[4] = {ap0.x, ap0.y, ap1.x, ap1.y};
            float4 bf = *(const float4*)&Bs[buf][k][tx * 4];
            u64 brp[4] = {pack2(bf.x, bf.x), pack2(bf.y, bf.y),
                          pack2(bf.z, bf.z), pack2(bf.w, bf.w)};
#pragma unroll
            for (int ip = 0; ip < 4; ip++)
#pragma unroll
                for (int j = 0; j < 4; j++)
                    accp[ip][j] = ffma2(arp[ip], brp[j], accp[ip][j]);
        }

        if (more) {
            int nb = buf ^ 1;
            As[nb][a_k + 0][a_r] = av.x;
            As[nb][a_k + 1][a_r] = av.y;
            *(float4*)&Bs[nb][b_k][b_c] = bv;
            __syncthreads();
            buf = nb;
        }
    }

    float4 bia = *(const float4*)(bias + tx * 4);
#pragma unroll
    for (int ip = 0; ip < 4; ip++) {
        float2 v0 = unpack2(accp[ip][0]);
        float2 v1 = unpack2(accp[ip][1]);
        float2 v2 = unpack2(accp[ip][2]);
        float2 v3 = unpack2(accp[ip][3]);
#pragma unroll
        for (int h = 0; h < 2; h++) {
            int r = rowBase + ty * 8 + ip * 2 + h;
            if (r >= M) continue;
            float o0 = (h ? v0.y : v0.x) + bia.x;
            float o1 = (h ? v1.y : v1.x) + bia.y;
            float o2 = (h ? v2.y : v2.x) + bia.z;
            float o3 = (h ? v3.y : v3.x) + bia.w;
            if (act == 1) {
                o0 = (o0 > 0.f) ? o0 : LEAK * o0;
                o1 = (o1 > 0.f) ? o1 : LEAK * o1;
                o2 = (o2 > 0.f) ? o2 : LEAK * o2;
                o3 = (o3 > 0.f) ? o3 : LEAK * o3;
            }
            *(float4*)(C + (size_t)r * ldc + tx * 4) = make_float4(o0, o1, o2, o3);
        }
    }
}

// ---------------------------------------------------------------------------
// Fused W1 GEMM + LayerNorm + leaky, FFMA2 mainloop (row-paired accp[4][8]).
// Strip-mapped cols {tx*4..+3} and {128+tx*4..+3} (conflict-free smem).
// ---------------------------------------------------------------------------
__global__ void __launch_bounds__(256, 2)
gemm_w1_ln_kernel(const float* __restrict__ A,       // [M,256] = z
                  const float* __restrict__ B,       // [256,256] = W1
                  const float* __restrict__ bias,    // [256]
                  const float* __restrict__ lng,     // [256]
                  const float* __restrict__ lnb,     // [256]
                  float* __restrict__ C,             // [M,256] = t1
                  int M) {
    __shared__ float As[2][8][64];
    __shared__ float Bs[2][8][256];

    int tid = threadIdx.x;
    int tx = tid & 31;
    int ty = tid >> 5;
    int rowBase = blockIdx.x * 64;

    int a_r = tid >> 2;
    int a_k = (tid & 3) << 1;
    int b_k = tid >> 5;
    int b_c = (tid & 31) << 2;

    int gr = rowBase + a_r;
    bool a_ok = (gr < M);
    const float* Aptr = A + (size_t)((gr < M) ? gr : 0) * 256 + a_k;
    const float* Bptr = B + (size_t)b_k * 256 + b_c;

    u64 accp[4][8];
#pragma unroll
    for (int i = 0; i < 4; i++)
#pragma unroll
        for (int j = 0; j < 8; j++) accp[i][j] = 0ULL;

    float2 av = a_ok ? *(const float2*)(Aptr) : make_float2(0.f, 0.f);
    float4 bv0 = *(const float4*)(Bptr);
    float4 bv1 = *(const float4*)(Bptr + 128);
    As[0][a_k + 0][a_r] = av.x;
    As[0][a_k + 1][a_r] = av.y;
    *(float4*)&Bs[0][b_k][b_c]       = bv0;
    *(float4*)&Bs[0][b_k][b_c + 128] = bv1;
    __syncthreads();

    int buf = 0;
    for (int k0 = 0; k0 < 256; k0 += 8) {
        bool more = (k0 + 8) < 256;
        if (more) {
            av  = a_ok ? *(const float2*)(Aptr + k0 + 8) : make_float2(0.f, 0.f);
            bv0 = *(const float4*)(Bptr + (size_t)(k0 + 8) * 256);
            bv1 = *(const float4*)(Bptr + (size_t)(k0 + 8) * 256 + 128);
        }

#pragma unroll
        for (int k = 0; k < 8; k++) {
            ulonglong2 ap0 = *(const ulonglong2*)&As[buf][k][ty * 8];
            ulonglong2 ap1 = *(const ulonglong2*)&As[buf][k][ty * 8 + 4];
            u64 arp[4] = {ap0.x, ap0.y, ap1.x, ap1.y};
            float4 bf0 = *(const float4*)&Bs[buf][k][tx * 4];
            float4 bf1 = *(const float4*)&Bs[buf][k][tx * 4 + 128];
            u64 brp[8] = {pack2(bf0.x, bf0.x), pack2(bf0.y, bf0.y),
                          pack2(bf0.z, bf0.z), pack2(bf0.w, bf0.w),
                          pack2(bf1.x, bf1.x), pack2(bf1.y, bf1.y),
                          pack2(bf1.z, bf1.z), pack2(bf1.w, bf1.w)};
#pragma unroll
            for (int ip = 0; ip < 4; ip++)
#pragma unroll
                for (int j = 0; j < 8; j++)
                    accp[ip][j] = ffma2(arp[ip], brp[j], accp[ip][j]);
        }

        if (more) {
            int nb = buf ^ 1;
            As[nb][a_k + 0][a_r] = av.x;
            As[nb][a_k + 1][a_r] = av.y;
            *(float4*)&Bs[nb][b_k][b_c]       = bv0;
            *(float4*)&Bs[nb][b_k][b_c + 128] = bv1;
            __syncthreads();
            buf = nb;
        }
    }

    // Epilogue: +bias, per-row LN (warp reduction over 256 cols), affine+leaky.
    float4 bia0 = *(const float4*)(bias + tx * 4);
    float4 bia1 = *(const float4*)(bias + tx * 4 + 128);
    float4 g0 = *(const float4*)(lng + tx * 4);
    float4 g1 = *(const float4*)(lng + tx * 4 + 128);
    float4 q0 = *(const float4*)(lnb + tx * 4);
    float4 q1 = *(const float4*)(lnb + tx * 4 + 128);

#pragma unroll
    for (int ip = 0; ip < 4; ip++) {
        float2 va[8];
#pragma unroll
        for (int j = 0; j < 8; j++) va[j] = unpack2(accp[ip][j]);
#pragma unroll
        for (int h = 0; h < 2; h++) {
            float t[8];
            t[0] = (h ? va[0].y : va[0].x) + bia0.x;
            t[1] = (h ? va[1].y : va[1].x) + bia0.y;
            t[2] = (h ? va[2].y : va[2].x) + bia0.z;
            t[3] = (h ? va[3].y : va[3].x) + bia0.w;
            t[4] = (h ? va[4].y : va[4].x) + bia1.x;
            t[5] = (h ? va[5].y : va[5].x) + bia1.y;
            t[6] = (h ? va[6].y : va[6].x) + bia1.z;
            t[7] = (h ? va[7].y : va[7].x) + bia1.w;

            float sum = 0.f, sq = 0.f;
#pragma unroll
            for (int j = 0; j < 8; j++) {
                sum += t[j];
                sq = fmaf(t[j], t[j], sq);
            }
#pragma unroll
            for (int s = 16; s > 0; s >>= 1) {
                sum += __shfl_xor_sync(0xffffffffu, sum, s);
                sq  += __shfl_xor_sync(0xffffffffu, sq,  s);
            }
            float mean = sum * (1.f / 256.f);
            float var  = sq * (1.f / 256.f) - mean * mean;
            float rstd = rsqrtf(var + LNEPS);

            int r = rowBase + ty * 8 + ip * 2 + h;
            if (r >= M) continue;

            float o[8];
            o[0] = (t[0] - mean) * rstd * g0.x + q0.x;
            o[1] = (t[1] - mean) * rstd * g0.y + q0.y;
            o[2] = (t[2] - mean) * rstd * g0.z + q0.z;
            o[3] = (t[3] - mean) * rstd * g0.w + q0.w;
            o[4] = (t[4] - mean) * rstd * g1.x + q1.x;
            o[5] = (t[5] - mean) * rstd * g1.y + q1.y;
            o[6] = (t[6] - mean) * rstd * g1.z + q1.z;
            o[7] = (t[7] - mean) * rstd * g1.w + q1.w;
#pragma unroll
            for (int j = 0; j < 8; j++) o[j] = (o[j] > 0.f) ? o[j] : LEAK * o[j];

            float* cp = C + (size_t)r * 256 + tx * 4;
            *(float4*)(cp)       = make_float4(o[0], o[1], o[2], o[3]);
            *(float4*)(cp + 128) = make_float4(o[4], o[5], o[6], o[7]);
        }
    }
}

// ---------------------------------------------------------------------------
// Fused W2+W3:  h = (leaky(t1 @ W2 + b2)) @ W3 + b3. FFMA2 in both phases.
// Phase 1: row-paired accp[4][8] (as w1_ln), bias+leaky -> t2 parked in smem.
// Phase 2: col-paired acc2p[8][2]; W3 pairs free via 64-bit WS reads.
// ---------------------------------------------------------------------------
#define W23_SMEM_BYTES (64 * 256 * 4 + 2 * 8 * 64 * 4 + 2 * 8 * 256 * 4)  // 86016

__global__ void __launch_bounds__(256, 2)
gemm_w23_kernel(const float* __restrict__ A,       // [M,256] = t1
                const float* __restrict__ W2,      // [256,256]
                const float* __restrict__ b2,      // [256]
                const float* __restrict__ W3,      // [256,128]
                const float* __restrict__ b3,      // [128]
                float* __restrict__ C,             // h slice, ldc = 512
                int ldc, int M) {
    extern __shared__ float sdyn[];
    float* t2s = sdyn;                         // [64][256]
    float* Asb = sdyn + 64 * 256;              // [2][8][64]
    float* Bsb = Asb + 2 * 8 * 64;             // [2][8][256]
    float* Wsb = Bsb;                          // overlay [2][8][128] (phase 2)
#define AS(b, k, r) Asb[(b) * 512 + (k) * 64 + (r)]
#define BS(b, k, c) Bsb[(b) * 2048 + (k) * 256 + (c)]
#define WS(b, k, c) Wsb[(b) * 1024 + (k) * 128 + (c)]
#define T2S(r, c)   t2s[(r) * 256 + (c)]

    int tid = threadIdx.x;
    int tx = tid & 31;
    int ty = tid >> 5;
    int rowBase = blockIdx.x * 64;

    int a_r = tid >> 2;
    int a_k = (tid & 3) << 1;
    int b_k = tid >> 5;
    int b_c = (tid & 31) << 2;

    int gr = rowBase + a_r;
    bool a_ok = (gr < M);
    const float* Aptr = A + (size_t)((gr < M) ? gr : 0) * 256 + a_k;
    const float* Bptr = W2 + (size_t)b_k * 256 + b_c;

    // ---------------- Phase 1: t2 = leaky(t1 @ W2 + b2) -> smem ----------------
    u64 accp[4][8];
#pragma unroll
    for (int i = 0; i < 4; i++)
#pragma unroll
        for (int j = 0; j < 8; j++) accp[i][j] = 0ULL;

    float2 av = a_ok ? *(const float2*)(Aptr) : make_float2(0.f, 0.f);
    float4 bv0 = *(const float4*)(Bptr);
    float4 bv1 = *(const float4*)(Bptr + 128);
    AS(0, a_k + 0, a_r) = av.x;
    AS(0, a_k + 1, a_r) = av.y;
    *(float4*)&BS(0, b_k, b_c)       = bv0;
    *(float4*)&BS(0, b_k, b_c + 128) = bv1;
    __syncthreads();

    int buf = 0;
    for (int k0 = 0; k0 < 256; k0 += 8) {
        bool more = (k0 + 8) < 256;
        if (more) {
            av  = a_ok ? *(const float2*)(Aptr + k0 + 8) : make_float2(0.f, 0.f);
            bv0 = *(const float4*)(Bptr + (size_t)(k0 + 8) * 256);
            bv1 = *(const float4*)(Bptr + (size_t)(k0 + 8) * 256 + 128);
        }

#pragma unroll
        for (int k = 0; k < 8; k++) {
            ulonglong2 ap0 = *(const ulonglong2*)&AS(buf, k, ty * 8);
            ulonglong2 ap1 = *(const ulonglong2*)&AS(buf, k, ty * 8 + 4);
            u64 arp[4] = {ap0.x, ap0.y, ap1.x, ap1.y};
            float4 bf0 = *(const float4*)&BS(buf, k, tx * 4);
            float4 bf1 = *(const float4*)&BS(buf, k, tx * 4 + 128);
            u64 brp[8] = {pack2(bf0.x, bf0.x), pack2(bf0.y, bf0.y),
                          pack2(bf0.z, bf0.z), pack2(bf0.w, bf0.w),
                          pack2(bf1.x, bf1.x), pack2(bf1.y, bf1.y),
                          pack2(bf1.z, bf1.z), pack2(bf1.w, bf1.w)};
#pragma unroll
            for (int ip = 0; ip < 4; ip++)
#pragma unroll
                for (int j = 0; j < 8; j++)
                    accp[ip][j] = ffma2(arp[ip], brp[j], accp[ip][j]);
        }

        if (more) {
            int nb = buf ^ 1;
            AS(nb, a_k + 0, a_r) = av.x;
            AS(nb, a_k + 1, a_r) = av.y;
            *(float4*)&BS(nb, b_k, b_c)       = bv0;
            *(float4*)&BS(nb, b_k, b_c + 128) = bv1;
            __syncthreads();
            buf = nb;
        }
    }

    // bias + leaky, park t2 tile in smem (strip-mapped stores, conflict-free)
    {
        float4 bia0 = *(const float4*)(b2 + tx * 4);
        float4 bia1 = *(const float4*)(b2 + tx * 4 + 128);
#pragma unroll
        for (int ip = 0; ip < 4; ip++) {
            float2 va[8];
#pragma unroll
            for (int j = 0; j < 8; j++) va[j] = unpack2(accp[ip][j]);
#pragma unroll
            for (int h = 0; h < 2; h++) {
                float o[8];
                o[0] = (h ? va[0].y : va[0].x) + bia0.x;
                o[1] = (h ? va[1].y : va[1].x) + bia0.y;
                o[2] = (h ? va[2].y : va[2].x) + bia0.z;
                o[3] = (h ? va[3].y : va[3].x) + bia0.w;
                o[4] = (h ? va[4].y : va[4].x) + bia1.x;
                o[5] = (h ? va[5].y : va[5].x) + bia1.y;
                o[6] = (h ? va[6].y : va[6].x) + bia1.z;
                o[7] = (h ? va[7].y : va[7].x) + bia1.w;
#pragma unroll
                for (int j = 0; j < 8; j++) o[j] = (o[j] > 0.f) ? o[j] : LEAK * o[j];
                float* tp = &T2S(ty * 8 + ip * 2 + h, tx * 4);
                *(float4*)(tp)       = make_float4(o[0], o[1], o[2], o[3]);
                *(float4*)(tp + 128) = make_float4(o[4], o[5], o[6], o[7]);
            }
        }
    }
    __syncthreads();   // t2s complete; Bs mainloop reads all done -> reuse as Ws

    // ---------------- Phase 2: h = t2s @ W3 + b3 ----------------
    u64 acc2p[8][2];
#pragma unroll
    for (int i = 0; i < 8; i++) { acc2p[i][0] = 0ULL; acc2p[i][1] = 0ULL; }

    float4 wv = *(const float4*)(W3 + (size_t)b_k * 128 + b_c);
    *(float4*)&WS(0, b_k, b_c) = wv;
    __syncthreads();

    buf = 0;
    for (int k0 = 0; k0 < 256; k0 += 8) {
        bool more = (k0 + 8) < 256;
        if (more)
            wv = *(const float4*)(W3 + (size_t)(k0 + 8 + b_k) * 128 + b_c);

#pragma unroll
        for (int k = 0; k < 8; k++) {
            ulonglong2 wp = *(const ulonglong2*)&WS(buf, k, tx * 4);  // col pairs
#pragma unroll
            for (int i = 0; i < 8; i++) {
                float a = T2S(ty * 8 + i, k0 + k);   // warp-broadcast
                u64 ad = pack2(a, a);
                acc2p[i][0] = ffma2(ad, wp.x, acc2p[i][0]);
                acc2p[i][1] = ffma2(ad, wp.y, acc2p[i][1]);
            }
        }

        if (more) {
            int nb = buf ^ 1;
            *(float4*)&WS(nb, b_k, b_c) = wv;
            __syncthreads();
            buf = nb;
        }
    }

    float4 bia = *(const float4*)(b3 + tx * 4);
#pragma unroll
    for (int i = 0; i < 8; i++) {
        int r = rowBase + ty * 8 + i;
        if (r >= M) continue;
        float2 v0 = unpack2(acc2p[i][0]);
        float2 v1 = unpack2(acc2p[i][1]);
        *(float4*)(C + (size_t)r * ldc + tx * 4) =
            make_float4(v0.x + bia.x, v0.y + bia.y,
                        v1.x + bia.z, v1.y + bia.w);
    }
#undef AS
#undef BS
#undef WS
#undef T2S
}

// ---------------------------------------------------------------------------
// Host launcher
// ---------------------------------------------------------------------------
extern "C" void kernel_launch(void* const* d_in, const int* in_sizes, int n_in,
                              void* d_out, int out_size) {
    const float* x     = (const float*)d_in[0];
    const int*   ei    = (const int*)d_in[1];   // int32 view; stride auto-detected
    const float* ea    = (const float*)d_in[2];
    const float* in_W  = (const float*)d_in[3];
    const float* in_b  = (const float*)d_in[4];
    const float* eW    = (const float*)d_in[5];   // [3,256]
    const float* eB    = (const float*)d_in[6];   // [3,256]
    const float* W1    = (const float*)d_in[7];   // [3,256,256]
    const float* b1    = (const float*)d_in[8];   // [3,256]
    const float* ln_g  = (const float*)d_in[9];   // [3,256]
    const float* ln_b  = (const float*)d_in[10];  // [3,256]
    const float* W2    = (const float*)d_in[11];  // [3,256,256]
    const float* b2    = (const float*)d_in[12];  // [3,256]
    const float* W3    = (const float*)d_in[13];  // [3,256,128]
    const float* b3    = (const float*)d_in[14];  // [3,128]
    const float* out_W = (const float*)d_in[15];  // [512,128]
    const float* out_b = (const float*)d_in[16];  // [128]
    float* out = (float*)d_out;

    float *hid, *z, *t1;
    int *deg, *fill;
    cudaGetSymbolAddress((void**)&hid,  g_hidden);
    cudaGetSymbolAddress((void**)&z,    g_z);
    cudaGetSymbolAddress((void**)&t1,   g_t1);
    cudaGetSymbolAddress((void**)&deg,  g_deg);
    cudaGetSymbolAddress((void**)&fill, g_fill);

    cudaFuncSetAttribute(gemm_w23_kernel,
                         cudaFuncAttributeMaxDynamicSharedMemorySize,
                         W23_SMEM_BYTES);

    dim3 blk(256);
    int mTiles64 = (NN + 63) / 64;    // 157

    // ---- CSR build (once per launch, reused by all 3 layers) ----
    cudaMemsetAsync(deg,  0, NN * sizeof(int));
    cudaMemsetAsync(fill, 0, NN * sizeof(int));
    detect_idx_kernel<<<1, 256>>>(ei);
    convert_idx_kernel<<<(EE + 255) / 256, 256>>>(ei);
    scan_kernel<<<1, 1024>>>();
    fill_csr_kernel<<<(EE + 255) / 256, 256>>>(ea);

    // h0 = x @ in_W + in_b  ->  hidden[:, 0:128]
    gemm64x128_kernel<<<dim3(1, mTiles64), blk>>>(x, 128, in_W, 128, in_b,
                                                  hid, 512, NN, 128, 0);

    for (int l = 0; l < 3; l++) {
        int hoff = l * 128;
        // z = xc + segment_sum(relu(xc[src] + edge_proj))   (atomic-free, float4)
        gather_kernel<<<NN, 64>>>(x, hoff, eW + l * 256, eB + l * 256);
        // t1 = leaky(LN(z @ W1 + b1))   (fused epilogue)
        gemm_w1_ln_kernel<<<mTiles64, blk>>>(z, W1 + (size_t)l * 256 * 256,
                                             b1 + l * 256, ln_g + l * 256,
                                             ln_b + l * 256, t1, NN);
        // h_{l+1} = leaky(t1 @ W2 + b2) @ W3 + b3   (fused, t2 never hits gmem)
        gemm_w23_kernel<<<mTiles64, blk, W23_SMEM_BYTES>>>(
            t1, W2 + (size_t)l * 256 * 256, b2 + l * 256,
            W3 + (size_t)l * 256 * 128, b3 + l * 128,
            hid + (l + 1) * 128, 512, NN);
    }

    // out = hidden @ out_W + out_b
    gemm64x128_kernel<<<dim3(1, mTiles64), blk>>>(hid, 512, out_W, 128, out_b,
                                                  out, 128, NN, 512, 0);
}